// round 1
// baseline (speedup 1.0000x reference)
#include <cuda_runtime.h>
#include <math.h>

// ---------------------------------------------------------------------------
// WindowAttention fused kernel (fp32 baseline)
// One CTA per window. 192 threads. All intermediates in dynamic smem.
// ---------------------------------------------------------------------------

#define NTOK   49
#define NCH    96
#define NHEADS 3
#define HDIM   32
#define STRIDE 97              // padded row stride (bank-conflict-free)
#define SCALEF 0.17677669529663687f   // 32^-0.5

// smem layout (in floats)
#define OFF_A     0                       // xs         [49][97]
#define OFF_B     (OFF_A + NTOK*STRIDE)   // q / sp / ks / conv1out
#define OFF_C     (OFF_B + NTOK*STRIDE)   // k / spat
#define OFF_D     (OFF_C + NTOK*STRIDE)   // v (lives whole kernel)
#define OFF_E     (OFF_D + NTOK*STRIDE)   // attn(2401) / qs / out_c+spec
#define OFF_RPB   (OFF_E + NTOK*STRIDE)   // 169*3 = 507
#define OFF_NQ    (OFF_RPB + 507)         // 96
#define OFF_NK    (OFF_NQ + 96)           // 96
#define OFF_CATTN (OFF_NK + 96)           // 3*32*33 = 3168
#define SMEM_FLOATS (OFF_CATTN + 3168)
#define SMEM_BYTES  (SMEM_FLOATS * 4)     // 110528 B -> 2 CTAs/SM

// Register-tiled GEMM: OUT[49][96] = X[49][96] @ W[96][96] (+ bias)
// 168 active threads: thread owns 4 out-channels x 7 tokens.
__device__ __forceinline__ void gemm96(const float* Xs,
                                       const float* __restrict__ W,
                                       const float* __restrict__ bias,
                                       float* Os, int tid)
{
    if (tid < 168) {
        const int jg = tid / 7, tg = tid % 7;
        const int j0 = jg * 4, t0 = tg * 7;
        float acc[7][4];
        #pragma unroll
        for (int t = 0; t < 7; t++) {
            acc[t][0] = 0.f; acc[t][1] = 0.f; acc[t][2] = 0.f; acc[t][3] = 0.f;
        }
        const float4* Wr = reinterpret_cast<const float4*>(W);
        #pragma unroll 4
        for (int k = 0; k < 96; k++) {
            float4 w = Wr[k * 24 + jg];
            #pragma unroll
            for (int t = 0; t < 7; t++) {
                float xv = Xs[(t0 + t) * STRIDE + k];
                acc[t][0] += xv * w.x;
                acc[t][1] += xv * w.y;
                acc[t][2] += xv * w.z;
                acc[t][3] += xv * w.w;
            }
        }
        float b0 = 0.f, b1 = 0.f, b2 = 0.f, b3 = 0.f;
        if (bias) { b0 = bias[j0]; b1 = bias[j0+1]; b2 = bias[j0+2]; b3 = bias[j0+3]; }
        #pragma unroll
        for (int t = 0; t < 7; t++) {
            float* o = Os + (t0 + t) * STRIDE + j0;
            o[0] = acc[t][0] + b0;
            o[1] = acc[t][1] + b1;
            o[2] = acc[t][2] + b2;
            o[3] = acc[t][3] + b3;
        }
    }
}

__global__ __launch_bounds__(192) void winattn_kernel(
    const float* __restrict__ x,
    const float* __restrict__ rpb_table,
    const float* __restrict__ wq,    const float* __restrict__ bq,
    const float* __restrict__ wk,    const float* __restrict__ bk,
    const float* __restrict__ wv,    const float* __restrict__ bv,
    const float* __restrict__ w_ps,  const float* __restrict__ b_ps,
    const float* __restrict__ wq_sp, const float* __restrict__ wk_sp,
    const float* __restrict__ w_pc,  const float* __restrict__ b_pc,
    const float* __restrict__ conv1, const float* __restrict__ conv2,
    const float* __restrict__ w_proj,const float* __restrict__ b_proj,
    float* __restrict__ out)
{
    extern __shared__ float sm[];
    float* A     = sm + OFF_A;
    float* Bb    = sm + OFF_B;
    float* Cc    = sm + OFF_C;
    float* Dd    = sm + OFF_D;
    float* Ee    = sm + OFF_E;
    float* RPB   = sm + OFF_RPB;
    float* NQ    = sm + OFF_NQ;
    float* NK    = sm + OFF_NK;
    float* CAT   = sm + OFF_CATTN;

    const int tid = threadIdx.x;
    const int blk = blockIdx.x;

    // ---- load x window + rpb table ----
    const float* xg = x + (size_t)blk * (NTOK * NCH);
    for (int i = tid; i < NTOK * NCH; i += 192)
        A[(i / NCH) * STRIDE + (i % NCH)] = xg[i];
    for (int i = tid; i < 507; i += 192)
        RPB[i] = rpb_table[i];
    __syncthreads();

    // ---- q, k, v projections ----
    gemm96(A, wq, bq, Bb, tid);   // q -> B
    gemm96(A, wk, bk, Cc, tid);   // k -> C
    gemm96(A, wv, bv, Dd, tid);   // v -> D  (stays resident)
    __syncthreads();

    // ---- spatial attention, one head at a time ----
    for (int h = 0; h < NHEADS; h++) {
        const int ch0 = h * HDIM;
        // scores: attn[i][j] = scale * q_i . k_j + rpb
        for (int idx = tid; idx < 7 * NTOK; idx += 192) {
            int ig = idx / NTOK, j = idx % NTOK;
            int i0 = ig * 7;
            float acc[7];
            #pragma unroll
            for (int a = 0; a < 7; a++) acc[a] = 0.f;
            for (int d = 0; d < HDIM; d++) {
                float kv = Cc[j * STRIDE + ch0 + d];
                #pragma unroll
                for (int a = 0; a < 7; a++)
                    acc[a] += Bb[(i0 + a) * STRIDE + ch0 + d] * kv;
            }
            int r2 = j / 7, c2 = j % 7;
            #pragma unroll
            for (int a = 0; a < 7; a++) {
                int i = i0 + a;
                int r1 = i / 7, c1 = i % 7;
                int ridx = (r1 - r2 + 6) * 13 + (c1 - c2 + 6);
                Ee[i * NTOK + j] = acc[a] * SCALEF + RPB[ridx * 3 + h];
            }
        }
        __syncthreads();
        // softmax rows
        if (tid < NTOK) {
            float* row = Ee + tid * NTOK;
            float m = row[0];
            for (int j = 1; j < NTOK; j++) m = fmaxf(m, row[j]);
            float s = 0.f;
            for (int j = 0; j < NTOK; j++) { float e = expf(row[j] - m); row[j] = e; s += e; }
            float inv = 1.f / s;
            for (int j = 0; j < NTOK; j++) row[j] *= inv;
        }
        __syncthreads();
        // sp_head = attn @ v_head  -> overwrite q's columns in B (dead now)
        if (tid < 56) {
            int dg = tid / 7, tg = tid % 7;
            int d0 = dg * 4, t0 = tg * 7;
            float acc[7][4];
            #pragma unroll
            for (int t = 0; t < 7; t++) {
                acc[t][0] = 0.f; acc[t][1] = 0.f; acc[t][2] = 0.f; acc[t][3] = 0.f;
            }
            for (int m = 0; m < NTOK; m++) {
                float v0 = Dd[m * STRIDE + ch0 + d0 + 0];
                float v1 = Dd[m * STRIDE + ch0 + d0 + 1];
                float v2 = Dd[m * STRIDE + ch0 + d0 + 2];
                float v3 = Dd[m * STRIDE + ch0 + d0 + 3];
                #pragma unroll
                for (int t = 0; t < 7; t++) {
                    float a = Ee[(t0 + t) * NTOK + m];
                    acc[t][0] += a * v0; acc[t][1] += a * v1;
                    acc[t][2] += a * v2; acc[t][3] += a * v3;
                }
            }
            #pragma unroll
            for (int t = 0; t < 7; t++) {
                float* o = Bb + (t0 + t) * STRIDE + ch0 + d0;
                o[0] = acc[t][0]; o[1] = acc[t][1]; o[2] = acc[t][2]; o[3] = acc[t][3];
            }
        }
        __syncthreads();
    }

    // ---- spatial_x = sp @ w_ps + b_ps -> C (k dead) ----
    gemm96(Bb, w_ps, b_ps, Cc, tid);
    __syncthreads();
    // ---- qs -> E (attn scratch dead) ----
    gemm96(A, wq_sp, 0, Ee, tid);
    __syncthreads();
    // ---- ks -> B (sp dead) ----
    gemm96(A, wk_sp, 0, Bb, tid);
    __syncthreads();

    // ---- L2 norms over tokens, per channel ----
    if (tid < 96) {
        float s = 0.f;
        for (int t = 0; t < NTOK; t++) { float v = Ee[t * STRIDE + tid]; s += v * v; }
        NQ[tid] = fmaxf(sqrtf(s), 1e-12f);
    } else {
        int c = tid - 96;
        float s = 0.f;
        for (int t = 0; t < NTOK; t++) { float v = Bb[t * STRIDE + c]; s += v * v; }
        NK[c] = fmaxf(sqrtf(s), 1e-12f);
    }
    __syncthreads();

    // ---- cattn[h][d][e] = SCALE * ksn_d . qsn_e   (192 threads, 4x4 tiles) ----
    {
        int h = tid / 64, r = tid % 64;
        int d0 = (r / 8) * 4, e0 = (r % 8) * 4;
        int ch = h * HDIM;
        float acc[4][4];
        #pragma unroll
        for (int i = 0; i < 4; i++)
            #pragma unroll
            for (int j = 0; j < 4; j++) acc[i][j] = 0.f;
        for (int t = 0; t < NTOK; t++) {
            float kv[4], qv[4];
            #pragma unroll
            for (int i = 0; i < 4; i++) kv[i] = Bb[t * STRIDE + ch + d0 + i];
            #pragma unroll
            for (int j = 0; j < 4; j++) qv[j] = Ee[t * STRIDE + ch + e0 + j];
            #pragma unroll
            for (int i = 0; i < 4; i++)
                #pragma unroll
                for (int j = 0; j < 4; j++) acc[i][j] += kv[i] * qv[j];
        }
        #pragma unroll
        for (int i = 0; i < 4; i++) {
            float invk = 1.f / NK[ch + d0 + i];
            #pragma unroll
            for (int j = 0; j < 4; j++)
                CAT[h * 1056 + (d0 + i) * 33 + e0 + j] =
                    acc[i][j] * SCALEF * invk / NQ[ch + e0 + j];
        }
    }
    __syncthreads();
    // ---- cattn softmax over e (rows (h,d)) ----
    if (tid < 96) {
        float* row = CAT + (tid / 32) * 1056 + (tid % 32) * 33;
        float m = row[0];
        for (int e = 1; e < 32; e++) m = fmaxf(m, row[e]);
        float s = 0.f;
        for (int e = 0; e < 32; e++) { float ev = expf(row[e] - m); row[e] = ev; s += ev; }
        float inv = 1.f / s;
        for (int e = 0; e < 32; e++) row[e] *= inv;
    }
    __syncthreads();

    // ---- xc[t][h*32+d] = sum_e cattn[h][d][e] * v[t][h*32+e] -> A (xs dead) ----
    if (tid < 168) {
        int jg = tid / 7, tg = tid % 7;
        int c0 = jg * 4, t0 = tg * 7;
        int h = c0 / HDIM, d0 = c0 % HDIM, ch = h * HDIM;
        float acc[7][4];
        #pragma unroll
        for (int t = 0; t < 7; t++) {
            acc[t][0] = 0.f; acc[t][1] = 0.f; acc[t][2] = 0.f; acc[t][3] = 0.f;
        }
        for (int e = 0; e < HDIM; e++) {
            float w0 = CAT[h * 1056 + (d0 + 0) * 33 + e];
            float w1 = CAT[h * 1056 + (d0 + 1) * 33 + e];
            float w2 = CAT[h * 1056 + (d0 + 2) * 33 + e];
            float w3 = CAT[h * 1056 + (d0 + 3) * 33 + e];
            #pragma unroll
            for (int t = 0; t < 7; t++) {
                float vv = Dd[(t0 + t) * STRIDE + ch + e];
                acc[t][0] += w0 * vv; acc[t][1] += w1 * vv;
                acc[t][2] += w2 * vv; acc[t][3] += w3 * vv;
            }
        }
        #pragma unroll
        for (int t = 0; t < 7; t++) {
            float* o = A + (t0 + t) * STRIDE + c0;
            o[0] = acc[t][0]; o[1] = acc[t][1]; o[2] = acc[t][2]; o[3] = acc[t][3];
        }
    }
    __syncthreads();

    // ---- out_c = xc @ w_pc + b_pc -> E (qs dead) ----
    gemm96(A, w_pc, b_pc, Ee, tid);
    __syncthreads();

    // ---- depthwise conv1(v) + exact GELU -> B (ks dead) ----
    if (tid < 168) {
        int jg = tid / 7, tg = tid % 7;
        int c0 = jg * 4, t0 = tg * 7;
        float wc[9][4];
        #pragma unroll
        for (int s = 0; s < 9; s++)
            #pragma unroll
            for (int i = 0; i < 4; i++) wc[s][i] = conv1[s * 96 + c0 + i];
        for (int t = t0; t < t0 + 7; t++) {
            int r = t / 7, cc = t % 7;
            float acc[4] = {0.f, 0.f, 0.f, 0.f};
            #pragma unroll
            for (int dr = 0; dr < 3; dr++) {
                int rr = r + dr - 1;
                if (rr < 0 || rr > 6) continue;
                #pragma unroll
                for (int dc = 0; dc < 3; dc++) {
                    int c2 = cc + dc - 1;
                    if (c2 < 0 || c2 > 6) continue;
                    int tt = rr * 7 + c2;
                    #pragma unroll
                    for (int i = 0; i < 4; i++)
                        acc[i] += Dd[tt * STRIDE + c0 + i] * wc[dr * 3 + dc][i];
                }
            }
            #pragma unroll
            for (int i = 0; i < 4; i++) {
                float g = acc[i];
                Bb[t * STRIDE + c0 + i] = 0.5f * g * (1.f + erff(g * 0.70710678118654752f));
            }
        }
    }
    __syncthreads();

    // ---- depthwise conv2(gelu-out) -> spectral E += ----
    if (tid < 168) {
        int jg = tid / 7, tg = tid % 7;
        int c0 = jg * 4, t0 = tg * 7;
        float wc[9][4];
        #pragma unroll
        for (int s = 0; s < 9; s++)
            #pragma unroll
            for (int i = 0; i < 4; i++) wc[s][i] = conv2[s * 96 + c0 + i];
        for (int t = t0; t < t0 + 7; t++) {
            int r = t / 7, cc = t % 7;
            float acc[4] = {0.f, 0.f, 0.f, 0.f};
            #pragma unroll
            for (int dr = 0; dr < 3; dr++) {
                int rr = r + dr - 1;
                if (rr < 0 || rr > 6) continue;
                #pragma unroll
                for (int dc = 0; dc < 3; dc++) {
                    int c2 = cc + dc - 1;
                    if (c2 < 0 || c2 > 6) continue;
                    int tt = rr * 7 + c2;
                    #pragma unroll
                    for (int i = 0; i < 4; i++)
                        acc[i] += Bb[tt * STRIDE + c0 + i] * wc[dr * 3 + dc][i];
                }
            }
            #pragma unroll
            for (int i = 0; i < 4; i++)
                Ee[t * STRIDE + c0 + i] += acc[i];
        }
    }
    __syncthreads();

    // ---- final: out = spat @ Wp[0:96] + spec @ Wp[96:192] + b_proj ----
    if (tid < 168) {
        int jg = tid / 7, tg = tid % 7;
        int j0 = jg * 4, t0 = tg * 7;
        float acc[7][4];
        #pragma unroll
        for (int t = 0; t < 7; t++) {
            acc[t][0] = 0.f; acc[t][1] = 0.f; acc[t][2] = 0.f; acc[t][3] = 0.f;
        }
        const float4* Wr = reinterpret_cast<const float4*>(w_proj);
        #pragma unroll 2
        for (int k = 0; k < 96; k++) {
            float4 w1 = Wr[k * 24 + jg];
            float4 w2 = Wr[(k + 96) * 24 + jg];
            #pragma unroll
            for (int t = 0; t < 7; t++) {
                float sa = Cc[(t0 + t) * STRIDE + k];
                float sb = Ee[(t0 + t) * STRIDE + k];
                acc[t][0] += sa * w1.x + sb * w2.x;
                acc[t][1] += sa * w1.y + sb * w2.y;
                acc[t][2] += sa * w1.z + sb * w2.z;
                acc[t][3] += sa * w1.w + sb * w2.w;
            }
        }
        float4 bb = *reinterpret_cast<const float4*>(b_proj + j0);
        float* og = out + (size_t)blk * (NTOK * NCH);
        #pragma unroll
        for (int t = 0; t < 7; t++) {
            float4 r;
            r.x = acc[t][0] + bb.x;
            r.y = acc[t][1] + bb.y;
            r.z = acc[t][2] + bb.z;
            r.w = acc[t][3] + bb.w;
            *reinterpret_cast<float4*>(og + (t0 + t) * NCH + j0) = r;
        }
    }
}

extern "C" void kernel_launch(void* const* d_in, const int* in_sizes, int n_in,
                              void* d_out, int out_size)
{
    const float* x      = (const float*)d_in[0];
    const float* rpb    = (const float*)d_in[1];
    const float* wq     = (const float*)d_in[2];
    const float* bq     = (const float*)d_in[3];
    const float* wk     = (const float*)d_in[4];
    const float* bk     = (const float*)d_in[5];
    const float* wv     = (const float*)d_in[6];
    const float* bv     = (const float*)d_in[7];
    const float* w_ps   = (const float*)d_in[8];
    const float* b_ps   = (const float*)d_in[9];
    const float* wq_sp  = (const float*)d_in[10];
    const float* wk_sp  = (const float*)d_in[11];
    const float* w_pc   = (const float*)d_in[12];
    const float* b_pc   = (const float*)d_in[13];
    const float* conv1  = (const float*)d_in[14];
    const float* conv2  = (const float*)d_in[15];
    const float* w_proj = (const float*)d_in[16];
    const float* b_proj = (const float*)d_in[17];
    float* out = (float*)d_out;

    int nwin = in_sizes[0] / (NTOK * NCH);

    cudaFuncSetAttribute(winattn_kernel,
                         cudaFuncAttributeMaxDynamicSharedMemorySize, SMEM_BYTES);
    winattn_kernel<<<nwin, 192, SMEM_BYTES>>>(
        x, rpb, wq, bq, wk, bk, wv, bv, w_ps, b_ps,
        wq_sp, wk_sp, w_pc, b_pc, conv1, conv2, w_proj, b_proj, out);
}

// round 2
// speedup vs baseline: 1.1072x; 1.1072x over previous
#include <cuda_runtime.h>
#include <math.h>

// ---------------------------------------------------------------------------
// WindowAttention fused kernel, round 2: f32x2 (FFMA2) packed math everywhere,
// warp-parallel softmaxes, widened attention phases.
// One CTA per window, 192 threads, 111.9KB dynamic smem (2 CTAs/SM).
// ---------------------------------------------------------------------------

#define NTOK   49
#define NCH    96
#define NHEADS 3
#define HDIM   32
#define ST     98               // even padded row stride (8B-aligned pairs)
#define CST    34               // cattn row stride
#define SCALEF 0.17677669529663687f   // 32^-0.5

#define BUF     (NTOK*ST)                 // 4802
#define OFF_A   0
#define OFF_B   (OFF_A + BUF)
#define OFF_C   (OFF_B + BUF)
#define OFF_D   (OFF_C + BUF)
#define OFF_E   (OFF_D + BUF)
#define OFF_RPB (OFF_E + BUF)             // 507 used, pad 508
#define OFF_NQ  (OFF_RPB + 508)           // 96
#define OFF_NK  (OFF_NQ + 96)             // 96
#define OFF_CAT (OFF_NK + 96)             // 3*32*34 = 3264
#define SMEM_FLOATS (OFF_CAT + 3264)      // 27974
#define SMEM_BYTES  (SMEM_FLOATS * 4)     // 111896

typedef unsigned long long u64;

__device__ __forceinline__ u64 dup2(float x) {
    u64 r; asm("mov.b64 %0,{%1,%1};" : "=l"(r) : "f"(x)); return r;
}
__device__ __forceinline__ void fma2(u64& d, u64 a, u64 b) {
    asm("fma.rn.f32x2 %0,%1,%2,%0;" : "+l"(d) : "l"(a), "l"(b));
}
__device__ __forceinline__ float2 unp(u64 a) {
    float2 r; asm("mov.b64 {%0,%1},%2;" : "=f"(r.x), "=f"(r.y) : "l"(a)); return r;
}
__device__ __forceinline__ float hsum(u64 a) {
    float2 p = unp(a); return p.x + p.y;
}

// OUT[49][96] = X[49][96] @ W[96][96] (+bias). 168 threads, 4ch x 7tok tiles.
// f32x2 over channel pairs: per k -> 1 LDG.128 + 7 LDS + 7 pack + 14 FFMA2.
__device__ __forceinline__ void gemm96(const float* Xs,
                                       const float* __restrict__ W,
                                       const float* __restrict__ bias,
                                       float* Os, int tid)
{
    if (tid >= 168) return;
    const int jg = tid / 7, tg = tid % 7;
    const int j0 = jg * 4, t0 = tg * 7;
    u64 acc[7][2];
    #pragma unroll
    for (int t = 0; t < 7; t++) { acc[t][0] = 0ULL; acc[t][1] = 0ULL; }
    const ulonglong2* Wr = reinterpret_cast<const ulonglong2*>(W);
    #pragma unroll 4
    for (int k = 0; k < 96; k++) {
        ulonglong2 w = Wr[k * 24 + jg];
        #pragma unroll
        for (int t = 0; t < 7; t++) {
            u64 xd = dup2(Xs[(t0 + t) * ST + k]);
            fma2(acc[t][0], xd, w.x);
            fma2(acc[t][1], xd, w.y);
        }
    }
    float2 b01 = make_float2(0.f, 0.f), b23 = make_float2(0.f, 0.f);
    if (bias) {
        b01 = *reinterpret_cast<const float2*>(bias + j0);
        b23 = *reinterpret_cast<const float2*>(bias + j0 + 2);
    }
    #pragma unroll
    for (int t = 0; t < 7; t++) {
        float2 a0 = unp(acc[t][0]), a1 = unp(acc[t][1]);
        float* o = Os + (t0 + t) * ST + j0;
        o[0] = a0.x + b01.x; o[1] = a0.y + b01.y;
        o[2] = a1.x + b23.x; o[3] = a1.y + b23.y;
    }
}

__global__ __launch_bounds__(192, 2) void winattn_kernel(
    const float* __restrict__ x,
    const float* __restrict__ rpb_table,
    const float* __restrict__ wq,    const float* __restrict__ bq,
    const float* __restrict__ wk,    const float* __restrict__ bk,
    const float* __restrict__ wv,    const float* __restrict__ bv,
    const float* __restrict__ w_ps,  const float* __restrict__ b_ps,
    const float* __restrict__ wq_sp, const float* __restrict__ wk_sp,
    const float* __restrict__ w_pc,  const float* __restrict__ b_pc,
    const float* __restrict__ conv1, const float* __restrict__ conv2,
    const float* __restrict__ w_proj,const float* __restrict__ b_proj,
    float* __restrict__ out)
{
    extern __shared__ float sm[];
    float* A   = sm + OFF_A;
    float* Bb  = sm + OFF_B;
    float* Cc  = sm + OFF_C;
    float* Dd  = sm + OFF_D;
    float* Ee  = sm + OFF_E;
    float* RPB = sm + OFF_RPB;
    float* NQ  = sm + OFF_NQ;
    float* NK  = sm + OFF_NK;
    float* CAT = sm + OFF_CAT;

    const int tid  = threadIdx.x;
    const int blk  = blockIdx.x;
    const int warp = tid >> 5, lane = tid & 31;

    // ---- load x window (float4) + rpb table ----
    {
        const float4* xg4 = reinterpret_cast<const float4*>(x + (size_t)blk * (NTOK * NCH));
        for (int i4 = tid; i4 < NTOK * 24; i4 += 192) {
            float4 v = xg4[i4];
            int t = i4 / 24, c = (i4 % 24) * 4;
            float* p = A + t * ST + c;
            p[0] = v.x; p[1] = v.y; p[2] = v.z; p[3] = v.w;
        }
        for (int i = tid; i < 507; i += 192) RPB[i] = rpb_table[i];
    }
    __syncthreads();

    // ---- q, k, v projections ----
    gemm96(A, wq, bq, Bb, tid);
    gemm96(A, wk, bk, Cc, tid);
    gemm96(A, wv, bv, Dd, tid);
    __syncthreads();

    // ---- spatial attention, per head ----
    for (int h = 0; h < NHEADS; h++) {
        const int ch0 = h * HDIM;
        // scores: f32x2 over d (both operands natural pairs)
        for (int idx = tid; idx < 7 * NTOK; idx += 192) {
            int ig = idx / NTOK, j = idx % NTOK;
            int i0 = ig * 7;
            u64 acc[7];
            #pragma unroll
            for (int a = 0; a < 7; a++) acc[a] = 0ULL;
            const float* Kj = Cc + j * ST + ch0;
            const float* Qb = Bb + i0 * ST + ch0;
            #pragma unroll
            for (int d = 0; d < HDIM; d += 2) {
                u64 k2 = *reinterpret_cast<const u64*>(Kj + d);
                #pragma unroll
                for (int a = 0; a < 7; a++) {
                    u64 q2 = *reinterpret_cast<const u64*>(Qb + a * ST + d);
                    fma2(acc[a], q2, k2);
                }
            }
            int r2 = j / 7, c2 = j % 7;
            #pragma unroll
            for (int a = 0; a < 7; a++) {
                int i = i0 + a;
                int r1 = i / 7, c1 = i % 7;
                int ridx = (r1 - r2 + 6) * 13 + (c1 - c2 + 6);
                Ee[i * NTOK + j] = hsum(acc[a]) * SCALEF + RPB[ridx * 3 + h];
            }
        }
        __syncthreads();
        // warp-parallel softmax over 49 rows
        for (int r = warp; r < NTOK; r += 6) {
            float* row = Ee + r * NTOK;
            float e1 = row[lane];
            bool hi = (lane + 32) < NTOK;
            float e2 = hi ? row[lane + 32] : -3.4e38f;
            float m = fmaxf(e1, e2);
            #pragma unroll
            for (int o = 16; o > 0; o >>= 1) m = fmaxf(m, __shfl_xor_sync(0xffffffffu, m, o));
            float p1 = __expf(e1 - m);
            float p2 = hi ? __expf(e2 - m) : 0.f;
            float s = p1 + p2;
            #pragma unroll
            for (int o = 16; o > 0; o >>= 1) s += __shfl_xor_sync(0xffffffffu, s, o);
            float inv = 1.f / s;
            row[lane] = p1 * inv;
            if (hi) row[lane + 32] = p2 * inv;
        }
        __syncthreads();
        // sp_head = attn @ v_head : 112 threads, 2d x 7tok, f32x2 over d-pair
        if (tid < 112) {
            int dg = tid / 7, tg = tid % 7;
            int d0 = dg * 2, t0 = tg * 7;
            u64 acc[7];
            #pragma unroll
            for (int t = 0; t < 7; t++) acc[t] = 0ULL;
            for (int m = 0; m < NTOK; m++) {
                u64 v2 = *reinterpret_cast<const u64*>(Dd + m * ST + ch0 + d0);
                #pragma unroll
                for (int t = 0; t < 7; t++) {
                    u64 a2 = dup2(Ee[(t0 + t) * NTOK + m]);
                    fma2(acc[t], a2, v2);
                }
            }
            #pragma unroll
            for (int t = 0; t < 7; t++)
                *reinterpret_cast<u64*>(Bb + (t0 + t) * ST + ch0 + d0) = acc[t];
        }
        __syncthreads();
    }

    // ---- spatial_x = sp @ w_ps + b_ps -> C ----
    gemm96(Bb, w_ps, b_ps, Cc, tid);
    __syncthreads();
    gemm96(A, wq_sp, 0, Ee, tid);      // qs -> E
    __syncthreads();
    gemm96(A, wk_sp, 0, Bb, tid);      // ks -> B
    __syncthreads();

    // ---- inverse L2 norms per channel ----
    if (tid < 96) {
        float s = 0.f;
        for (int t = 0; t < NTOK; t++) { float v = Ee[t * ST + tid]; s += v * v; }
        NQ[tid] = rsqrtf(fmaxf(s, 1e-24f));
    } else {
        int c = tid - 96;
        float s = 0.f;
        for (int t = 0; t < NTOK; t++) { float v = Bb[t * ST + c]; s += v * v; }
        NK[c] = rsqrtf(fmaxf(s, 1e-24f));
    }
    __syncthreads();

    // ---- cattn[h][d][e] raw, 192 threads, 4x4 tiles, f32x2 over e ----
    {
        int h = tid / 64, r = tid % 64;
        int d0 = (r / 8) * 4, e0 = (r % 8) * 4;
        int ch = h * HDIM;
        u64 acc[4][2];
        #pragma unroll
        for (int i = 0; i < 4; i++) { acc[i][0] = 0ULL; acc[i][1] = 0ULL; }
        for (int t = 0; t < NTOK; t++) {
            u64 q0 = *reinterpret_cast<const u64*>(Ee + t * ST + ch + e0);
            u64 q1 = *reinterpret_cast<const u64*>(Ee + t * ST + ch + e0 + 2);
            #pragma unroll
            for (int i = 0; i < 4; i++) {
                u64 kd = dup2(Bb[t * ST + ch + d0 + i]);
                fma2(acc[i][0], kd, q0);
                fma2(acc[i][1], kd, q1);
            }
        }
        #pragma unroll
        for (int i = 0; i < 4; i++) {
            float invk = NK[ch + d0 + i] * SCALEF;
            float2 a0 = unp(acc[i][0]), a1 = unp(acc[i][1]);
            float* o = CAT + h * 1088 + (d0 + i) * CST + e0;
            o[0] = a0.x * invk * NQ[ch + e0 + 0];
            o[1] = a0.y * invk * NQ[ch + e0 + 1];
            o[2] = a1.x * invk * NQ[ch + e0 + 2];
            o[3] = a1.y * invk * NQ[ch + e0 + 3];
        }
    }
    __syncthreads();
    // ---- cattn softmax: warp per row, 96 rows of exactly 32 ----
    for (int rid = warp; rid < 96; rid += 6) {
        float* row = CAT + (rid >> 5) * 1088 + (rid & 31) * CST;
        float e = row[lane];
        float m = e;
        #pragma unroll
        for (int o = 16; o > 0; o >>= 1) m = fmaxf(m, __shfl_xor_sync(0xffffffffu, m, o));
        float p = __expf(e - m);
        float s = p;
        #pragma unroll
        for (int o = 16; o > 0; o >>= 1) s += __shfl_xor_sync(0xffffffffu, s, o);
        row[lane] = p * (1.f / s);
    }
    __syncthreads();

    // ---- xc = cattn @ v (per head) -> A. 168 threads, f32x2 over e ----
    if (tid < 168) {
        int jg = tid / 7, tg = tid % 7;
        int c0 = jg * 4, t0 = tg * 7;
        int h = c0 / HDIM, d0 = c0 % HDIM, ch = h * HDIM;
        const float* CR = CAT + h * 1088;
        u64 acc[7][4];
        #pragma unroll
        for (int t = 0; t < 7; t++)
            #pragma unroll
            for (int i = 0; i < 4; i++) acc[t][i] = 0ULL;
        #pragma unroll 4
        for (int e = 0; e < HDIM; e += 2) {
            u64 w0 = *reinterpret_cast<const u64*>(CR + (d0 + 0) * CST + e);
            u64 w1 = *reinterpret_cast<const u64*>(CR + (d0 + 1) * CST + e);
            u64 w2 = *reinterpret_cast<const u64*>(CR + (d0 + 2) * CST + e);
            u64 w3 = *reinterpret_cast<const u64*>(CR + (d0 + 3) * CST + e);
            #pragma unroll
            for (int t = 0; t < 7; t++) {
                u64 v2 = *reinterpret_cast<const u64*>(Dd + (t0 + t) * ST + ch + e);
                fma2(acc[t][0], v2, w0);
                fma2(acc[t][1], v2, w1);
                fma2(acc[t][2], v2, w2);
                fma2(acc[t][3], v2, w3);
            }
        }
        #pragma unroll
        for (int t = 0; t < 7; t++) {
            float* o = A + (t0 + t) * ST + c0;
            o[0] = hsum(acc[t][0]); o[1] = hsum(acc[t][1]);
            o[2] = hsum(acc[t][2]); o[3] = hsum(acc[t][3]);
        }
    }
    __syncthreads();

    // ---- out_c = xc @ w_pc + b_pc -> E ----
    gemm96(A, w_pc, b_pc, Ee, tid);
    __syncthreads();

    // ---- conv1(v) + exact GELU -> B ----
    if (tid < 168) {
        int jg = tid / 7, tg = tid % 7;
        int c0 = jg * 4, t0 = tg * 7;
        u64 wc[9][2];
        #pragma unroll
        for (int s = 0; s < 9; s++) {
            wc[s][0] = *reinterpret_cast<const u64*>(conv1 + s * 96 + c0);
            wc[s][1] = *reinterpret_cast<const u64*>(conv1 + s * 96 + c0 + 2);
        }
        for (int t = t0; t < t0 + 7; t++) {
            int r = t / 7, cc = t % 7;
            u64 a0 = 0ULL, a1 = 0ULL;
            #pragma unroll
            for (int dr = 0; dr < 3; dr++) {
                int rr = r + dr - 1;
                if (rr < 0 || rr > 6) continue;
                #pragma unroll
                for (int dc = 0; dc < 3; dc++) {
                    int c2 = cc + dc - 1;
                    if (c2 < 0 || c2 > 6) continue;
                    const float* vp = Dd + (rr * 7 + c2) * ST + c0;
                    fma2(a0, *reinterpret_cast<const u64*>(vp), wc[dr * 3 + dc][0]);
                    fma2(a1, *reinterpret_cast<const u64*>(vp + 2), wc[dr * 3 + dc][1]);
                }
            }
            float2 p0 = unp(a0), p1 = unp(a1);
            float* o = Bb + t * ST + c0;
            o[0] = 0.5f * p0.x * (1.f + erff(p0.x * 0.70710678118654752f));
            o[1] = 0.5f * p0.y * (1.f + erff(p0.y * 0.70710678118654752f));
            o[2] = 0.5f * p1.x * (1.f + erff(p1.x * 0.70710678118654752f));
            o[3] = 0.5f * p1.y * (1.f + erff(p1.y * 0.70710678118654752f));
        }
    }
    __syncthreads();

    // ---- conv2(gelu) -> E += ----
    if (tid < 168) {
        int jg = tid / 7, tg = tid % 7;
        int c0 = jg * 4, t0 = tg * 7;
        u64 wc[9][2];
        #pragma unroll
        for (int s = 0; s < 9; s++) {
            wc[s][0] = *reinterpret_cast<const u64*>(conv2 + s * 96 + c0);
            wc[s][1] = *reinterpret_cast<const u64*>(conv2 + s * 96 + c0 + 2);
        }
        for (int t = t0; t < t0 + 7; t++) {
            int r = t / 7, cc = t % 7;
            u64 a0 = 0ULL, a1 = 0ULL;
            #pragma unroll
            for (int dr = 0; dr < 3; dr++) {
                int rr = r + dr - 1;
                if (rr < 0 || rr > 6) continue;
                #pragma unroll
                for (int dc = 0; dc < 3; dc++) {
                    int c2 = cc + dc - 1;
                    if (c2 < 0 || c2 > 6) continue;
                    const float* vp = Bb + (rr * 7 + c2) * ST + c0;
                    fma2(a0, *reinterpret_cast<const u64*>(vp), wc[dr * 3 + dc][0]);
                    fma2(a1, *reinterpret_cast<const u64*>(vp + 2), wc[dr * 3 + dc][1]);
                }
            }
            float2 p0 = unp(a0), p1 = unp(a1);
            float* o = Ee + t * ST + c0;
            o[0] += p0.x; o[1] += p0.y; o[2] += p1.x; o[3] += p1.y;
        }
    }
    __syncthreads();

    // ---- final: out = spat @ Wp[0:96] + spec @ Wp[96:192] + b_proj ----
    if (tid < 168) {
        int jg = tid / 7, tg = tid % 7;
        int j0 = jg * 4, t0 = tg * 7;
        u64 acc[7][2];
        #pragma unroll
        for (int t = 0; t < 7; t++) { acc[t][0] = 0ULL; acc[t][1] = 0ULL; }
        const ulonglong2* Wr = reinterpret_cast<const ulonglong2*>(w_proj);
        #pragma unroll 2
        for (int k = 0; k < 96; k++) {
            ulonglong2 wa = Wr[k * 24 + jg];
            ulonglong2 wb = Wr[(k + 96) * 24 + jg];
            #pragma unroll
            for (int t = 0; t < 7; t++) {
                u64 sa = dup2(Cc[(t0 + t) * ST + k]);
                u64 sb = dup2(Ee[(t0 + t) * ST + k]);
                fma2(acc[t][0], sa, wa.x);
                fma2(acc[t][1], sa, wa.y);
                fma2(acc[t][0], sb, wb.x);
                fma2(acc[t][1], sb, wb.y);
            }
        }
        float2 b01 = *reinterpret_cast<const float2*>(b_proj + j0);
        float2 b23 = *reinterpret_cast<const float2*>(b_proj + j0 + 2);
        float* og = out + (size_t)blk * (NTOK * NCH);
        #pragma unroll
        for (int t = 0; t < 7; t++) {
            float2 a0 = unp(acc[t][0]), a1 = unp(acc[t][1]);
            float4 r;
            r.x = a0.x + b01.x; r.y = a0.y + b01.y;
            r.z = a1.x + b23.x; r.w = a1.y + b23.y;
            *reinterpret_cast<float4*>(og + (t0 + t) * NCH + j0) = r;
        }
    }
}

extern "C" void kernel_launch(void* const* d_in, const int* in_sizes, int n_in,
                              void* d_out, int out_size)
{
    const float* x      = (const float*)d_in[0];
    const float* rpb    = (const float*)d_in[1];
    const float* wq     = (const float*)d_in[2];
    const float* bq     = (const float*)d_in[3];
    const float* wk     = (const float*)d_in[4];
    const float* bk     = (const float*)d_in[5];
    const float* wv     = (const float*)d_in[6];
    const float* bv     = (const float*)d_in[7];
    const float* w_ps   = (const float*)d_in[8];
    const float* b_ps   = (const float*)d_in[9];
    const float* wq_sp  = (const float*)d_in[10];
    const float* wk_sp  = (const float*)d_in[11];
    const float* w_pc   = (const float*)d_in[12];
    const float* b_pc   = (const float*)d_in[13];
    const float* conv1  = (const float*)d_in[14];
    const float* conv2  = (const float*)d_in[15];
    const float* w_proj = (const float*)d_in[16];
    const float* b_proj = (const float*)d_in[17];
    float* out = (float*)d_out;

    int nwin = in_sizes[0] / (NTOK * NCH);

    cudaFuncSetAttribute(winattn_kernel,
                         cudaFuncAttributeMaxDynamicSharedMemorySize, SMEM_BYTES);
    winattn_kernel<<<nwin, 192, SMEM_BYTES>>>(
        x, rpb, wq, bq, wk, bk, wv, bv, w_ps, b_ps,
        wq_sp, wk_sp, w_pc, b_pc, conv1, conv2, w_proj, b_proj, out);
}

// round 3
// speedup vs baseline: 1.1093x; 1.0019x over previous
#include <cuda_runtime.h>
#include <math.h>

// ---------------------------------------------------------------------------
// WindowAttention fused kernel, round 3: LDS.64 everywhere (halve shared-mem
// wavefronts), f32x2 FFMA2 math, warp-parallel softmaxes.
// One CTA per window, 192 threads, ~112KB dynamic smem (2 CTAs/SM).
// ---------------------------------------------------------------------------

#define NTOK   49
#define NCH    96
#define NHEADS 3
#define HDIM   32
#define ST     98               // even padded row stride (8B-aligned pairs)
#define AST    50               // attn scratch row stride (even!)
#define CST    34               // cattn row stride
#define SCALEF 0.17677669529663687f   // 32^-0.5

#define BUF     (NTOK*ST)                 // 4802
#define OFF_A   0
#define OFF_B   (OFF_A + BUF)
#define OFF_C   (OFF_B + BUF)
#define OFF_D   (OFF_C + BUF)
#define OFF_E   (OFF_D + BUF)
#define OFF_RPB (OFF_E + BUF)             // 507 used, pad 508
#define OFF_NQ  (OFF_RPB + 508)           // 96
#define OFF_NK  (OFF_NQ + 96)             // 96
#define OFF_CAT (OFF_NK + 96)             // 3*32*34 = 3264
#define SMEM_FLOATS (OFF_CAT + 3264)
#define SMEM_BYTES  (SMEM_FLOATS * 4)     // 111896

typedef unsigned long long u64;

__device__ __forceinline__ u64 dup2(float x) {
    u64 r; asm("mov.b64 %0,{%1,%1};" : "=l"(r) : "f"(x)); return r;
}
__device__ __forceinline__ void fma2(u64& d, u64 a, u64 b) {
    asm("fma.rn.f32x2 %0,%1,%2,%0;" : "+l"(d) : "l"(a), "l"(b));
}
__device__ __forceinline__ float2 unp(u64 a) {
    float2 r; asm("mov.b64 {%0,%1},%2;" : "=f"(r.x), "=f"(r.y) : "l"(a)); return r;
}
__device__ __forceinline__ float hsum(u64 a) {
    float2 p = unp(a); return p.x + p.y;
}
__device__ __forceinline__ u64 lds64(const float* p) {
    return *reinterpret_cast<const u64*>(p);
}

// OUT[49][96] = X[49][96] @ W[96][96] (+bias). 168 threads, 4ch x 7tok tiles.
// k-loop by pairs: per 2k per token: 1 LDS.64 + 4 dup-mov + 4 FFMA2.
__device__ __forceinline__ void gemm96(const float* Xs,
                                       const float* __restrict__ W,
                                       const float* __restrict__ bias,
                                       float* Os, int tid)
{
    if (tid >= 168) return;
    const int jg = tid / 7, tg = tid % 7;
    const int j0 = jg * 4, t0 = tg * 7;
    u64 acc[7][2];
    #pragma unroll
    for (int t = 0; t < 7; t++) { acc[t][0] = 0ULL; acc[t][1] = 0ULL; }
    const ulonglong2* Wr = reinterpret_cast<const ulonglong2*>(W);
    #pragma unroll 2
    for (int k = 0; k < 96; k += 2) {
        ulonglong2 w0 = Wr[k * 24 + jg];
        ulonglong2 w1 = Wr[(k + 1) * 24 + jg];
        #pragma unroll
        for (int t = 0; t < 7; t++) {
            float2 xp = unp(lds64(Xs + (t0 + t) * ST + k));
            u64 d0 = dup2(xp.x), d1 = dup2(xp.y);
            fma2(acc[t][0], d0, w0.x);
            fma2(acc[t][1], d0, w0.y);
            fma2(acc[t][0], d1, w1.x);
            fma2(acc[t][1], d1, w1.y);
        }
    }
    float2 b01 = make_float2(0.f, 0.f), b23 = make_float2(0.f, 0.f);
    if (bias) {
        b01 = *reinterpret_cast<const float2*>(bias + j0);
        b23 = *reinterpret_cast<const float2*>(bias + j0 + 2);
    }
    #pragma unroll
    for (int t = 0; t < 7; t++) {
        float2 a0 = unp(acc[t][0]), a1 = unp(acc[t][1]);
        float* o = Os + (t0 + t) * ST + j0;
        o[0] = a0.x + b01.x; o[1] = a0.y + b01.y;
        o[2] = a1.x + b23.x; o[3] = a1.y + b23.y;
    }
}

__global__ __launch_bounds__(192, 2) void winattn_kernel(
    const float* __restrict__ x,
    const float* __restrict__ rpb_table,
    const float* __restrict__ wq,    const float* __restrict__ bq,
    const float* __restrict__ wk,    const float* __restrict__ bk,
    const float* __restrict__ wv,    const float* __restrict__ bv,
    const float* __restrict__ w_ps,  const float* __restrict__ b_ps,
    const float* __restrict__ wq_sp, const float* __restrict__ wk_sp,
    const float* __restrict__ w_pc,  const float* __restrict__ b_pc,
    const float* __restrict__ conv1, const float* __restrict__ conv2,
    const float* __restrict__ w_proj,const float* __restrict__ b_proj,
    float* __restrict__ out)
{
    extern __shared__ float sm[];
    float* A   = sm + OFF_A;
    float* Bb  = sm + OFF_B;
    float* Cc  = sm + OFF_C;
    float* Dd  = sm + OFF_D;
    float* Ee  = sm + OFF_E;
    float* RPB = sm + OFF_RPB;
    float* NQ  = sm + OFF_NQ;
    float* NK  = sm + OFF_NK;
    float* CAT = sm + OFF_CAT;

    const int tid  = threadIdx.x;
    const int blk  = blockIdx.x;
    const int warp = tid >> 5, lane = tid & 31;

    // ---- load x window (float4) + rpb table ----
    {
        const float4* xg4 = reinterpret_cast<const float4*>(x + (size_t)blk * (NTOK * NCH));
        for (int i4 = tid; i4 < NTOK * 24; i4 += 192) {
            float4 v = xg4[i4];
            int t = i4 / 24, c = (i4 % 24) * 4;
            float* p = A + t * ST + c;
            p[0] = v.x; p[1] = v.y; p[2] = v.z; p[3] = v.w;
        }
        for (int i = tid; i < 507; i += 192) RPB[i] = rpb_table[i];
    }
    __syncthreads();

    // ---- q, k, v projections ----
    gemm96(A, wq, bq, Bb, tid);
    gemm96(A, wk, bk, Cc, tid);
    gemm96(A, wv, bv, Dd, tid);
    __syncthreads();

    // ---- spatial attention, per head ----
    for (int h = 0; h < NHEADS; h++) {
        const int ch0 = h * HDIM;
        // scores: f32x2 over d pairs (LDS.64 both sides), scratch stride AST
        for (int idx = tid; idx < 7 * NTOK; idx += 192) {
            int ig = idx / NTOK, j = idx % NTOK;
            int i0 = ig * 7;
            u64 acc[7];
            #pragma unroll
            for (int a = 0; a < 7; a++) acc[a] = 0ULL;
            const float* Kj = Cc + j * ST + ch0;
            const float* Qb = Bb + i0 * ST + ch0;
            #pragma unroll
            for (int d = 0; d < HDIM; d += 2) {
                u64 k2 = lds64(Kj + d);
                #pragma unroll
                for (int a = 0; a < 7; a++)
                    fma2(acc[a], lds64(Qb + a * ST + d), k2);
            }
            int r2 = j / 7, c2 = j % 7;
            #pragma unroll
            for (int a = 0; a < 7; a++) {
                int i = i0 + a;
                int r1 = i / 7, c1 = i % 7;
                int ridx = (r1 - r2 + 6) * 13 + (c1 - c2 + 6);
                Ee[i * AST + j] = hsum(acc[a]) * SCALEF + RPB[ridx * 3 + h];
            }
        }
        __syncthreads();
        // warp-parallel softmax over 49 rows
        for (int r = warp; r < NTOK; r += 6) {
            float* row = Ee + r * AST;
            float e1 = row[lane];
            bool hi = (lane + 32) < NTOK;
            float e2 = hi ? row[lane + 32] : -3.4e38f;
            float m = fmaxf(e1, e2);
            #pragma unroll
            for (int o = 16; o > 0; o >>= 1) m = fmaxf(m, __shfl_xor_sync(0xffffffffu, m, o));
            float p1 = __expf(e1 - m);
            float p2 = hi ? __expf(e2 - m) : 0.f;
            float s = p1 + p2;
            #pragma unroll
            for (int o = 16; o > 0; o >>= 1) s += __shfl_xor_sync(0xffffffffu, s, o);
            float inv = 1.f / s;
            row[lane] = p1 * inv;
            if (hi) row[lane + 32] = p2 * inv;
        }
        __syncthreads();
        // sp_head = attn @ v_head : 112 threads, 2d x 7tok, m-pairs (LDS.64 attn)
        if (tid < 112) {
            int dg = tid / 7, tg = tid % 7;
            int d0 = dg * 2, t0 = tg * 7;
            u64 acc[7];
            #pragma unroll
            for (int t = 0; t < 7; t++) acc[t] = 0ULL;
            #pragma unroll 4
            for (int m = 0; m < 48; m += 2) {
                u64 v2a = lds64(Dd + m * ST + ch0 + d0);
                u64 v2b = lds64(Dd + (m + 1) * ST + ch0 + d0);
                #pragma unroll
                for (int t = 0; t < 7; t++) {
                    float2 ap = unp(lds64(Ee + (t0 + t) * AST + m));
                    fma2(acc[t], dup2(ap.x), v2a);
                    fma2(acc[t], dup2(ap.y), v2b);
                }
            }
            {   // tail m = 48
                u64 v2a = lds64(Dd + 48 * ST + ch0 + d0);
                #pragma unroll
                for (int t = 0; t < 7; t++)
                    fma2(acc[t], dup2(Ee[(t0 + t) * AST + 48]), v2a);
            }
            #pragma unroll
            for (int t = 0; t < 7; t++)
                *reinterpret_cast<u64*>(Bb + (t0 + t) * ST + ch0 + d0) = acc[t];
        }
        __syncthreads();
    }

    // ---- spatial_x = sp @ w_ps + b_ps -> C ----
    gemm96(Bb, w_ps, b_ps, Cc, tid);
    __syncthreads();
    gemm96(A, wq_sp, 0, Ee, tid);      // qs -> E
    __syncthreads();
    gemm96(A, wk_sp, 0, Bb, tid);      // ks -> B
    __syncthreads();

    // ---- inverse L2 norms per channel ----
    if (tid < 96) {
        float s = 0.f;
        for (int t = 0; t < NTOK; t++) { float v = Ee[t * ST + tid]; s += v * v; }
        NQ[tid] = rsqrtf(fmaxf(s, 1e-24f));
    } else {
        int c = tid - 96;
        float s = 0.f;
        for (int t = 0; t < NTOK; t++) { float v = Bb[t * ST + c]; s += v * v; }
        NK[c] = rsqrtf(fmaxf(s, 1e-24f));
    }
    __syncthreads();

    // ---- cattn[h][d][e] raw: 192 threads, 4x4 tiles, LDS.64 both sides ----
    {
        int h = tid / 64, r = tid % 64;
        int d0 = (r / 8) * 4, e0 = (r % 8) * 4;
        int ch = h * HDIM;
        u64 acc[4][2];
        #pragma unroll
        for (int i = 0; i < 4; i++) { acc[i][0] = 0ULL; acc[i][1] = 0ULL; }
        for (int t = 0; t < NTOK; t++) {
            u64 q0 = lds64(Ee + t * ST + ch + e0);
            u64 q1 = lds64(Ee + t * ST + ch + e0 + 2);
            float2 k01 = unp(lds64(Bb + t * ST + ch + d0));
            float2 k23 = unp(lds64(Bb + t * ST + ch + d0 + 2));
            u64 kd0 = dup2(k01.x), kd1 = dup2(k01.y);
            u64 kd2 = dup2(k23.x), kd3 = dup2(k23.y);
            fma2(acc[0][0], kd0, q0); fma2(acc[0][1], kd0, q1);
            fma2(acc[1][0], kd1, q0); fma2(acc[1][1], kd1, q1);
            fma2(acc[2][0], kd2, q0); fma2(acc[2][1], kd2, q1);
            fma2(acc[3][0], kd3, q0); fma2(acc[3][1], kd3, q1);
        }
        #pragma unroll
        for (int i = 0; i < 4; i++) {
            float invk = NK[ch + d0 + i] * SCALEF;
            float2 a0 = unp(acc[i][0]), a1 = unp(acc[i][1]);
            float* o = CAT + h * 1088 + (d0 + i) * CST + e0;
            o[0] = a0.x * invk * NQ[ch + e0 + 0];
            o[1] = a0.y * invk * NQ[ch + e0 + 1];
            o[2] = a1.x * invk * NQ[ch + e0 + 2];
            o[3] = a1.y * invk * NQ[ch + e0 + 3];
        }
    }
    __syncthreads();
    // ---- cattn softmax: warp per row, 96 rows of exactly 32 ----
    for (int rid = warp; rid < 96; rid += 6) {
        float* row = CAT + (rid >> 5) * 1088 + (rid & 31) * CST;
        float e = row[lane];
        float m = e;
        #pragma unroll
        for (int o = 16; o > 0; o >>= 1) m = fmaxf(m, __shfl_xor_sync(0xffffffffu, m, o));
        float p = __expf(e - m);
        float s = p;
        #pragma unroll
        for (int o = 16; o > 0; o >>= 1) s += __shfl_xor_sync(0xffffffffu, s, o);
        row[lane] = p * (1.f / s);
    }
    __syncthreads();

    // ---- xc = cattn @ v (per head) -> A. 168 threads, f32x2 over e ----
    if (tid < 168) {
        int jg = tid / 7, tg = tid % 7;
        int c0 = jg * 4, t0 = tg * 7;
        int h = c0 / HDIM, d0 = c0 % HDIM, ch = h * HDIM;
        const float* CR = CAT + h * 1088;
        u64 acc[7][4];
        #pragma unroll
        for (int t = 0; t < 7; t++)
            #pragma unroll
            for (int i = 0; i < 4; i++) acc[t][i] = 0ULL;
        #pragma unroll 4
        for (int e = 0; e < HDIM; e += 2) {
            u64 w0 = lds64(CR + (d0 + 0) * CST + e);
            u64 w1 = lds64(CR + (d0 + 1) * CST + e);
            u64 w2 = lds64(CR + (d0 + 2) * CST + e);
            u64 w3 = lds64(CR + (d0 + 3) * CST + e);
            #pragma unroll
            for (int t = 0; t < 7; t++) {
                u64 v2 = lds64(Dd + (t0 + t) * ST + ch + e);
                fma2(acc[t][0], v2, w0);
                fma2(acc[t][1], v2, w1);
                fma2(acc[t][2], v2, w2);
                fma2(acc[t][3], v2, w3);
            }
        }
        #pragma unroll
        for (int t = 0; t < 7; t++) {
            float* o = A + (t0 + t) * ST + c0;
            o[0] = hsum(acc[t][0]); o[1] = hsum(acc[t][1]);
            o[2] = hsum(acc[t][2]); o[3] = hsum(acc[t][3]);
        }
    }
    __syncthreads();

    // ---- out_c = xc @ w_pc + b_pc -> E ----
    gemm96(A, w_pc, b_pc, Ee, tid);
    __syncthreads();

    // ---- conv1(v) + exact GELU -> B ----
    if (tid < 168) {
        int jg = tid / 7, tg = tid % 7;
        int c0 = jg * 4, t0 = tg * 7;
        u64 wc[9][2];
        #pragma unroll
        for (int s = 0; s < 9; s++) {
            wc[s][0] = *reinterpret_cast<const u64*>(conv1 + s * 96 + c0);
            wc[s][1] = *reinterpret_cast<const u64*>(conv1 + s * 96 + c0 + 2);
        }
        for (int t = t0; t < t0 + 7; t++) {
            int r = t / 7, cc = t % 7;
            u64 a0 = 0ULL, a1 = 0ULL;
            #pragma unroll
            for (int dr = 0; dr < 3; dr++) {
                int rr = r + dr - 1;
                if (rr < 0 || rr > 6) continue;
                #pragma unroll
                for (int dc = 0; dc < 3; dc++) {
                    int c2 = cc + dc - 1;
                    if (c2 < 0 || c2 > 6) continue;
                    const float* vp = Dd + (rr * 7 + c2) * ST + c0;
                    fma2(a0, lds64(vp), wc[dr * 3 + dc][0]);
                    fma2(a1, lds64(vp + 2), wc[dr * 3 + dc][1]);
                }
            }
            float2 p0 = unp(a0), p1 = unp(a1);
            float* o = Bb + t * ST + c0;
            o[0] = 0.5f * p0.x * (1.f + erff(p0.x * 0.70710678118654752f));
            o[1] = 0.5f * p0.y * (1.f + erff(p0.y * 0.70710678118654752f));
            o[2] = 0.5f * p1.x * (1.f + erff(p1.x * 0.70710678118654752f));
            o[3] = 0.5f * p1.y * (1.f + erff(p1.y * 0.70710678118654752f));
        }
    }
    __syncthreads();

    // ---- conv2(gelu) -> E += ----
    if (tid < 168) {
        int jg = tid / 7, tg = tid % 7;
        int c0 = jg * 4, t0 = tg * 7;
        u64 wc[9][2];
        #pragma unroll
        for (int s = 0; s < 9; s++) {
            wc[s][0] = *reinterpret_cast<const u64*>(conv2 + s * 96 + c0);
            wc[s][1] = *reinterpret_cast<const u64*>(conv2 + s * 96 + c0 + 2);
        }
        for (int t = t0; t < t0 + 7; t++) {
            int r = t / 7, cc = t % 7;
            u64 a0 = 0ULL, a1 = 0ULL;
            #pragma unroll
            for (int dr = 0; dr < 3; dr++) {
                int rr = r + dr - 1;
                if (rr < 0 || rr > 6) continue;
                #pragma unroll
                for (int dc = 0; dc < 3; dc++) {
                    int c2 = cc + dc - 1;
                    if (c2 < 0 || c2 > 6) continue;
                    const float* vp = Bb + (rr * 7 + c2) * ST + c0;
                    fma2(a0, lds64(vp), wc[dr * 3 + dc][0]);
                    fma2(a1, lds64(vp + 2), wc[dr * 3 + dc][1]);
                }
            }
            float2 p0 = unp(a0), p1 = unp(a1);
            float* o = Ee + t * ST + c0;
            o[0] += p0.x; o[1] += p0.y; o[2] += p1.x; o[3] += p1.y;
        }
    }
    __syncthreads();

    // ---- final: out = spat @ Wp[0:96] + spec @ Wp[96:192] + b_proj ----
    if (tid < 168) {
        int jg = tid / 7, tg = tid % 7;
        int j0 = jg * 4, t0 = tg * 7;
        u64 acc[7][2];
        #pragma unroll
        for (int t = 0; t < 7; t++) { acc[t][0] = 0ULL; acc[t][1] = 0ULL; }
        const ulonglong2* Wr = reinterpret_cast<const ulonglong2*>(w_proj);
        for (int k = 0; k < 96; k += 2) {
            ulonglong2 wa0 = Wr[k * 24 + jg];
            ulonglong2 wa1 = Wr[(k + 1) * 24 + jg];
            ulonglong2 wb0 = Wr[(k + 96) * 24 + jg];
            ulonglong2 wb1 = Wr[(k + 97) * 24 + jg];
            #pragma unroll
            for (int t = 0; t < 7; t++) {
                float2 sa = unp(lds64(Cc + (t0 + t) * ST + k));
                float2 sb = unp(lds64(Ee + (t0 + t) * ST + k));
                fma2(acc[t][0], dup2(sa.x), wa0.x);
                fma2(acc[t][1], dup2(sa.x), wa0.y);
                fma2(acc[t][0], dup2(sa.y), wa1.x);
                fma2(acc[t][1], dup2(sa.y), wa1.y);
                fma2(acc[t][0], dup2(sb.x), wb0.x);
                fma2(acc[t][1], dup2(sb.x), wb0.y);
                fma2(acc[t][0], dup2(sb.y), wb1.x);
                fma2(acc[t][1], dup2(sb.y), wb1.y);
            }
        }
        float2 b01 = *reinterpret_cast<const float2*>(b_proj + j0);
        float2 b23 = *reinterpret_cast<const float2*>(b_proj + j0 + 2);
        float* og = out + (size_t)blk * (NTOK * NCH);
        #pragma unroll
        for (int t = 0; t < 7; t++) {
            float2 a0 = unp(acc[t][0]), a1 = unp(acc[t][1]);
            float4 r;
            r.x = a0.x + b01.x; r.y = a0.y + b01.y;
            r.z = a1.x + b23.x; r.w = a1.y + b23.y;
            *reinterpret_cast<float4*>(og + (t0 + t) * NCH + j0) = r;
        }
    }
}

extern "C" void kernel_launch(void* const* d_in, const int* in_sizes, int n_in,
                              void* d_out, int out_size)
{
    const float* x      = (const float*)d_in[0];
    const float* rpb    = (const float*)d_in[1];
    const float* wq     = (const float*)d_in[2];
    const float* bq     = (const float*)d_in[3];
    const float* wk     = (const float*)d_in[4];
    const float* bk     = (const float*)d_in[5];
    const float* wv     = (const float*)d_in[6];
    const float* bv     = (const float*)d_in[7];
    const float* w_ps   = (const float*)d_in[8];
    const float* b_ps   = (const float*)d_in[9];
    const float* wq_sp  = (const float*)d_in[10];
    const float* wk_sp  = (const float*)d_in[11];
    const float* w_pc   = (const float*)d_in[12];
    const float* b_pc   = (const float*)d_in[13];
    const float* conv1  = (const float*)d_in[14];
    const float* conv2  = (const float*)d_in[15];
    const float* w_proj = (const float*)d_in[16];
    const float* b_proj = (const float*)d_in[17];
    float* out = (float*)d_out;

    int nwin = in_sizes[0] / (NTOK * NCH);

    cudaFuncSetAttribute(winattn_kernel,
                         cudaFuncAttributeMaxDynamicSharedMemorySize, SMEM_BYTES);
    winattn_kernel<<<nwin, 192, SMEM_BYTES>>>(
        x, rpb, wq, bq, wk, bk, wv, bv, w_ps, b_ps,
        wq_sp, wk_sp, w_pc, b_pc, conv1, conv2, w_proj, b_proj, out);
}